// round 14
// baseline (speedup 1.0000x reference)
#include <cuda_runtime.h>
#include <cuda_fp16.h>
#include <math.h>
#include <stdint.h>

// Problem constants
#define B_   32
#define N_   1024
#define E_   16384
#define D_   128
#define M_   (B_*N_)      // 32768
#define KB_  256
#define H_   8
#define HD_  16
#define EPSF 1e-6f

#define OFF_SV (M_*D_)
#define OFF_MK (OFF_SV + B_*258)
#define OFF_ST (OFF_MK + M_)

// rounded/transposed-weight scratch offsets (halves). layout: [n][K]
#define WR_E1L0 0         // K=128
#define WR_E1L1 16384     // K=128
#define WR_E2L0 32768     // K=128
#define WR_E2L1 49152     // K=128
#define WR_WG   65536     // K=256
#define WR_WU   98304     // K=256
#define WR_WOUT 131072    // K=128
#define WR_TOT  147456

// ---------------- scratch (activations in fp16) ----------------
__device__ __half g_h   [M_*D_];
__device__ __half g_t   [2*M_*D_];
__device__ __half g_fhb [2*M_*D_];
__device__ __half g_accb[2*M_*D_];
__device__ __half g_hb  [2*M_*D_];
__device__ __half g_q2  [M_*D_];
__device__ __half g_k2  [B_*KB_*D_];
__device__ __half g_v2  [B_*KB_*D_];
__device__ __half g_oh  [M_*D_];
__device__ float  g_hnum [B_*128];
__device__ float  g_hmean[B_*128];
__device__ float  g_part [B_*8*128];
__device__ __half g_Wf  [3*256*128];   // transposed [n][256] per segment
__device__ float  g_bf  [3*128];
__device__ __half g_Wr  [WR_TOT];
__device__ __half g_Abf [2L*B_*N_*N_]; // adjacency counts (134MB)

// ---------------- helpers ----------------
__device__ __forceinline__ void mma_f16(float c[4], const uint32_t a[4], const uint32_t b[2]) {
    asm volatile(
        "mma.sync.aligned.m16n8k16.row.col.f32.f16.f16.f32 "
        "{%0,%1,%2,%3}, {%4,%5,%6,%7}, {%8,%9}, {%0,%1,%2,%3};"
        : "+f"(c[0]), "+f"(c[1]), "+f"(c[2]), "+f"(c[3])
        : "r"(a[0]), "r"(a[1]), "r"(a[2]), "r"(a[3]), "r"(b[0]), "r"(b[1]));
}

__device__ __forceinline__ void cp16(uint32_t dst, const void* src) {
    asm volatile("cp.async.ca.shared.global [%0], [%1], 16;" :: "r"(dst), "l"(src));
}
__device__ __forceinline__ void cp8(uint32_t dst, const void* src) {
    asm volatile("cp.async.ca.shared.global [%0], [%1], 8;" :: "r"(dst), "l"(src));
}
__device__ __forceinline__ uint32_t s2u(const void* p) {
    return (uint32_t)__cvta_generic_to_shared(p);
}
#define CP_COMMIT() asm volatile("cp.async.commit_group;")
#define CP_WAIT(n)  asm volatile("cp.async.wait_group %0;" :: "n"(n))

// fast exp on FMA pipe
__device__ __forceinline__ float fexp(float x) {
    x = fmaxf(x, -87.0f);
    float t = x * 1.4426950408889634f;
    float fn = rintf(t);
    float f = t - fn;
    float p = 1.3333558146e-3f;
    p = fmaf(p, f, 9.6179662376e-3f);
    p = fmaf(p, f, 5.5490420128e-2f);
    p = fmaf(p, f, 2.4022650696e-1f);
    p = fmaf(p, f, 6.9314718056e-1f);
    p = fmaf(p, f, 1.0f);
    int n = (int)fn;
    float sc = __int_as_float((n + 127) << 23);
    return p * sc;
}

// ---- round + transpose input weights into half scratch [n][K] ---------------
__global__ void round_k(const float* __restrict__ ew1, const float* __restrict__ ew2,
                        const float* __restrict__ Wg,  const float* __restrict__ Wu,
                        const float* __restrict__ Wout, __half* __restrict__ Wr)
{
    int i = blockIdx.x * 256 + threadIdx.x;   // 576*256 = 147456
    float v; int base, K;
    if      (i < 16384)  { v = ew1[32768 + i];            base = WR_E1L0; K = 128; }
    else if (i < 32768)  { v = ew1[49152 + (i - 16384)];  base = WR_E1L1; K = 128; }
    else if (i < 49152)  { v = ew2[32768 + (i - 32768)];  base = WR_E2L0; K = 128; }
    else if (i < 65536)  { v = ew2[49152 + (i - 49152)];  base = WR_E2L1; K = 128; }
    else if (i < 98304)  { v = Wg[i - 65536];             base = WR_WG;   K = 256; }
    else if (i < 131072) { v = Wu[i - 98304];             base = WR_WU;   K = 256; }
    else                 { v = Wout[i - 131072];          base = WR_WOUT; K = 128; }
    int local = i - base;
    int k = local >> 7, n = local & 127;      // source is [k][128]
    Wr[base + n * K + k] = __float2half_rn(v);
}

// ------- fp16 GEMM (K=128), cp.async double-buffer, dual-branch --------------
// W transposed [n][128]. epi: 0 none, 1 tanh. outFloat: write fp32 C.
__global__ void __launch_bounds__(256, 2) tgemm2h_k(
    const __half* __restrict__ A0p, const __half* __restrict__ A1p,
    const __half* __restrict__ W0p, const __half* __restrict__ W1p,
    const float* __restrict__ b0p, const float* __restrict__ b1p,
    void* C0p, void* C1p,
    int epi, int outFloat)
{
    const int br = blockIdx.y;
    const __half* A    = br ? A1p : A0p;
    const __half* Wt   = br ? W1p : W0p;
    const float*  bias = br ? b1p : b0p;
    void*         C    = br ? C1p : C0p;

    __shared__ __half As[2][128][24];
    __shared__ __half Bs[2][128][24];
    const int tid = threadIdx.x;
    const int m0  = blockIdx.x * 128;
    const int warp = tid >> 5, lane = tid & 31;
    const int m0w = (warp >> 2) * 64, n0w = (warp & 3) * 32;
    const int g = lane >> 2, tig = lane & 3;

    const int arow = tid >> 1, ac8 = (tid & 1) * 8;
    const long abase = (long)(m0 + arow) * 128;

    float c[4][4][4];
    #pragma unroll
    for (int mf = 0; mf < 4; mf++)
        #pragma unroll
        for (int nf = 0; nf < 4; nf++)
            #pragma unroll
            for (int q = 0; q < 4; q++) c[mf][nf][q] = 0.f;

    cp16(s2u(&As[0][arow][ac8]), &A[abase + ac8]);
    cp16(s2u(&Bs[0][arow][ac8]), &Wt[(long)arow * 128 + ac8]);
    CP_COMMIT();

    int buf = 0;
    for (int k0 = 0; k0 < 128; k0 += 16) {
        bool nxt = (k0 + 16) < 128;
        if (nxt) {
            int kn = k0 + 16;
            cp16(s2u(&As[buf ^ 1][arow][ac8]), &A[abase + kn + ac8]);
            cp16(s2u(&Bs[buf ^ 1][arow][ac8]), &Wt[(long)arow * 128 + kn + ac8]);
            CP_COMMIT();
            CP_WAIT(1);
        } else CP_WAIT(0);
        __syncthreads();
        uint32_t b[4][2];
        #pragma unroll
        for (int nf = 0; nf < 4; nf++) {
            int nc = n0w + nf * 8 + g;
            b[nf][0] = *(const uint32_t*)&Bs[buf][nc][2 * tig];
            b[nf][1] = *(const uint32_t*)&Bs[buf][nc][2 * tig + 8];
        }
        #pragma unroll
        for (int mf = 0; mf < 4; mf++) {
            int mcol = m0w + mf * 16 + g;
            uint32_t a[4];
            a[0] = *(const uint32_t*)&As[buf][mcol    ][2 * tig];
            a[1] = *(const uint32_t*)&As[buf][mcol + 8][2 * tig];
            a[2] = *(const uint32_t*)&As[buf][mcol    ][2 * tig + 8];
            a[3] = *(const uint32_t*)&As[buf][mcol + 8][2 * tig + 8];
            #pragma unroll
            for (int nf = 0; nf < 4; nf++)
                mma_f16(c[mf][nf], a, b[nf]);
        }
        __syncthreads();
        buf ^= 1;
    }
    #pragma unroll
    for (int mf = 0; mf < 4; mf++) {
        int row0 = m0 + m0w + mf * 16 + g;
        #pragma unroll
        for (int nf = 0; nf < 4; nf++) {
            int col = n0w + nf * 8 + 2 * tig;
            float b0 = bias[col], b1 = bias[col + 1];
            float v00 = c[mf][nf][0] + b0, v01 = c[mf][nf][1] + b1;
            float v10 = c[mf][nf][2] + b0, v11 = c[mf][nf][3] + b1;
            if (epi == 1) { v00 = tanhf(v00); v01 = tanhf(v01); v10 = tanhf(v10); v11 = tanhf(v11); }
            if (outFloat) {
                float* Cf = (float*)C;
                *(float2*)&Cf[(long)row0 * 128 + col]       = make_float2(v00, v01);
                *(float2*)&Cf[(long)(row0 + 8) * 128 + col] = make_float2(v10, v11);
            } else {
                __half* Ch = (__half*)C;
                *(__half2*)&Ch[(long)row0 * 128 + col]       = __floats2half2_rn(v00, v01);
                *(__half2*)&Ch[(long)(row0 + 8) * 128 + col] = __floats2half2_rn(v10, v11);
            }
        }
    }
}

// ---- q2/k2/v2 merged fp16 GEMM (K=256 concat hb0|hb1), 384 blocks -----------
__global__ void __launch_bounds__(256, 2) qkvh_k(
    const __half* __restrict__ hb0, const __half* __restrict__ hb1,
    const int* __restrict__ bidx,
    const __half* __restrict__ Wf, const float* __restrict__ bf,
    __half* __restrict__ q2, __half* __restrict__ k2, __half* __restrict__ v2)
{
    const int x = blockIdx.x;
    const int seg = (x < 256) ? 0 : (x < 320 ? 1 : 2);
    const int mb  = (seg == 0) ? x : (seg == 1 ? x - 256 : x - 320);
    const int m0  = mb * 128;
    const __half* Wt   = Wf + seg * 32768;    // transposed [n][256]
    const float*  bias = bf + seg * 128;
    __half* C = (seg == 0) ? q2 : (seg == 1 ? k2 : v2);

    __shared__ __half As[2][128][24];
    __shared__ __half Bs[2][128][24];
    const int tid = threadIdx.x;
    const int warp = tid >> 5, lane = tid & 31;
    const int m0w = (warp >> 2) * 64, n0w = (warp & 3) * 32;
    const int g = lane >> 2, tig = lane & 3;

    const int arow = tid >> 1, ac8 = (tid & 1) * 8;
    int pr;
    { int gm = m0 + arow; pr = (seg == 0) ? gm : (gm / KB_) * N_ + bidx[gm % KB_]; }
    const long abase = (long)pr * 128;

    float c[4][4][4];
    #pragma unroll
    for (int mf = 0; mf < 4; mf++)
        #pragma unroll
        for (int nf = 0; nf < 4; nf++)
            #pragma unroll
            for (int q = 0; q < 4; q++) c[mf][nf][q] = 0.f;

    auto asrc = [&](int k) -> const __half* {
        return (k < 128) ? &hb0[abase + k] : &hb1[abase + (k - 128)];
    };

    cp16(s2u(&As[0][arow][ac8]), asrc(ac8));
    cp16(s2u(&Bs[0][arow][ac8]), &Wt[(long)arow * 256 + ac8]);
    CP_COMMIT();

    int buf = 0;
    for (int k0 = 0; k0 < 256; k0 += 16) {
        bool nxt = (k0 + 16) < 256;
        if (nxt) {
            int kn = k0 + 16;
            cp16(s2u(&As[buf ^ 1][arow][ac8]), asrc(kn + ac8));
            cp16(s2u(&Bs[buf ^ 1][arow][ac8]), &Wt[(long)arow * 256 + kn + ac8]);
            CP_COMMIT();
            CP_WAIT(1);
        } else CP_WAIT(0);
        __syncthreads();
        uint32_t b[4][2];
        #pragma unroll
        for (int nf = 0; nf < 4; nf++) {
            int nc = n0w + nf * 8 + g;
            b[nf][0] = *(const uint32_t*)&Bs[buf][nc][2 * tig];
            b[nf][1] = *(const uint32_t*)&Bs[buf][nc][2 * tig + 8];
        }
        #pragma unroll
        for (int mf = 0; mf < 4; mf++) {
            int mcol = m0w + mf * 16 + g;
            uint32_t a[4];
            a[0] = *(const uint32_t*)&As[buf][mcol    ][2 * tig];
            a[1] = *(const uint32_t*)&As[buf][mcol + 8][2 * tig];
            a[2] = *(const uint32_t*)&As[buf][mcol    ][2 * tig + 8];
            a[3] = *(const uint32_t*)&As[buf][mcol + 8][2 * tig + 8];
            #pragma unroll
            for (int nf = 0; nf < 4; nf++)
                mma_f16(c[mf][nf], a, b[nf]);
        }
        __syncthreads();
        buf ^= 1;
    }
    #pragma unroll
    for (int mf = 0; mf < 4; mf++) {
        int row0 = m0 + m0w + mf * 16 + g;
        #pragma unroll
        for (int nf = 0; nf < 4; nf++) {
            int col = n0w + nf * 8 + 2 * tig;
            float b0 = bias[col], b1 = bias[col + 1];
            *(__half2*)&C[(long)row0 * 128 + col] =
                __floats2half2_rn(c[mf][nf][0] + b0, c[mf][nf][1] + b1);
            *(__half2*)&C[(long)(row0 + 8) * 128 + col] =
                __floats2half2_rn(c[mf][nf][2] + b0, c[mf][nf][3] + b1);
        }
    }
}

// ---- adjacency aggregation fp16; deg via fragment rowsum; scaled output -----
// A (counts, half) via cp.async; B (fh) register-staged transposed to [n][k].
__global__ void __launch_bounds__(256, 2) adjh_k(
    const __half* __restrict__ Abf,
    const __half* __restrict__ fhb,
    __half* __restrict__ accb)
{
    __shared__ __half As[2][128][24];
    __shared__ __half Bs[2][128][24];
    __shared__ float degS[128];
    const int tid = threadIdx.x;
    const int bb = blockIdx.y, br = blockIdx.z;
    const int m0 = blockIdx.x * 128;
    const int warp = tid >> 5, lane = tid & 31;
    const int m0w = (warp >> 2) * 64, n0w = (warp & 3) * 32;
    const int g = lane >> 2, tig = lane & 3;
    const __half* Ab = Abf + (long)br * B_ * N_ * N_ + (long)bb * N_ * N_;
    const __half* fhp = fhb + (long)br * M_ * D_ + (long)bb * N_ * D_;
    __half* accp = accb + (long)br * M_ * D_;

    const int arow = tid >> 1, ac8 = (tid & 1) * 8;
    const int krow = tid >> 4, nc8 = (tid & 15) * 8;   // B stage

    float c[4][4][4];
    float ds0[4], ds1[4];
    #pragma unroll
    for (int mf = 0; mf < 4; mf++) {
        ds0[mf] = 0.f; ds1[mf] = 0.f;
        #pragma unroll
        for (int nf = 0; nf < 4; nf++)
            #pragma unroll
            for (int q = 0; q < 4; q++) c[mf][nf][q] = 0.f;
    }

    auto bstage = [&](int buf, uint4 raw) {
        const __half* hp = (const __half*)&raw;
        #pragma unroll
        for (int j = 0; j < 8; j++)
            Bs[buf][nc8 + j][krow] = hp[j];
    };

    // prologue
    cp16(s2u(&As[0][arow][ac8]), Ab + (long)(m0 + arow) * N_ + ac8);
    CP_COMMIT();
    uint4 r0 = *(const uint4*)(fhp + (long)krow * D_ + nc8);
    bstage(0, r0);

    int buf = 0;
    for (int k0 = 0; k0 < N_; k0 += 16) {
        bool nxt = (k0 + 16) < N_;
        uint4 r2;
        if (nxt) {
            int kn = k0 + 16;
            cp16(s2u(&As[buf ^ 1][arow][ac8]), Ab + (long)(m0 + arow) * N_ + kn + ac8);
            CP_COMMIT();
            r2 = *(const uint4*)(fhp + (long)(kn + krow) * D_ + nc8);
            CP_WAIT(1);
        } else CP_WAIT(0);
        __syncthreads();
        uint32_t b[4][2];
        #pragma unroll
        for (int nf = 0; nf < 4; nf++) {
            int nc = n0w + nf * 8 + g;
            b[nf][0] = *(const uint32_t*)&Bs[buf][nc][2 * tig];
            b[nf][1] = *(const uint32_t*)&Bs[buf][nc][2 * tig + 8];
        }
        #pragma unroll
        for (int mf = 0; mf < 4; mf++) {
            int mcol = m0w + mf * 16 + g;
            uint32_t a[4];
            a[0] = *(const uint32_t*)&As[buf][mcol    ][2 * tig];
            a[1] = *(const uint32_t*)&As[buf][mcol + 8][2 * tig];
            a[2] = *(const uint32_t*)&As[buf][mcol    ][2 * tig + 8];
            a[3] = *(const uint32_t*)&As[buf][mcol + 8][2 * tig + 8];
            float2 f0 = __half22float2(*(const __half2*)&a[0]);
            float2 f1 = __half22float2(*(const __half2*)&a[1]);
            float2 f2 = __half22float2(*(const __half2*)&a[2]);
            float2 f3 = __half22float2(*(const __half2*)&a[3]);
            ds0[mf] += f0.x + f0.y + f2.x + f2.y;
            ds1[mf] += f1.x + f1.y + f3.x + f3.y;
            #pragma unroll
            for (int nf = 0; nf < 4; nf++)
                mma_f16(c[mf][nf], a, b[nf]);
        }
        if (nxt) bstage(buf ^ 1, r2);
        __syncthreads();
        buf ^= 1;
    }
    // reduce rowsums over tig lanes; n0w==0 warps publish
    #pragma unroll
    for (int mf = 0; mf < 4; mf++) {
        float d0 = ds0[mf], d1 = ds1[mf];
        d0 += __shfl_xor_sync(0xffffffffu, d0, 1);
        d0 += __shfl_xor_sync(0xffffffffu, d0, 2);
        d1 += __shfl_xor_sync(0xffffffffu, d1, 1);
        d1 += __shfl_xor_sync(0xffffffffu, d1, 2);
        if ((warp & 3) == 0 && tig == 0) {
            degS[m0w + mf * 16 + g]     = d0;
            degS[m0w + mf * 16 + g + 8] = d1;
        }
    }
    __syncthreads();
    #pragma unroll
    for (int mf = 0; mf < 4; mf++) {
        int rowl = m0w + mf * 16 + g;
        int row0 = bb * N_ + m0 + rowl;
        float s0 = 1.0f / (degS[rowl] + EPSF);
        float s1 = 1.0f / (degS[rowl + 8] + EPSF);
        #pragma unroll
        for (int nf = 0; nf < 4; nf++) {
            int col = n0w + nf * 8 + 2 * tig;
            *(__half2*)&accp[(long)row0 * 128 + col] =
                __floats2half2_rn(c[mf][nf][0] * s0, c[mf][nf][1] * s0);
            *(__half2*)&accp[(long)(row0 + 8) * 128 + col] =
                __floats2half2_rn(c[mf][nf][2] * s1, c[mf][nf][3] * s1);
        }
    }
}

// ---- fused gate+update+combine dual fp16 GEMM -------------------------------
__global__ void __launch_bounds__(256, 2) guh_k(
    const __half* __restrict__ h,
    const __half* __restrict__ accb,
    const __half* __restrict__ WgT, const float* __restrict__ bg,
    const __half* __restrict__ WuT, const float* __restrict__ bu,
    __half* __restrict__ houtb)
{
    const int br = blockIdx.y;
    const __half* acc = accb + (long)br * M_ * D_;
    __half* hout = houtb + (long)br * M_ * D_;

    __shared__ __half As [2][64][24];
    __shared__ __half BsG[2][128][24];
    __shared__ __half BsU[2][128][24];
    const int tid = threadIdx.x;
    const int m0 = blockIdx.x * 64;
    const int warp = tid >> 5, lane = tid & 31;
    const int m0w = (warp >> 2) * 32, n0w = (warp & 3) * 32;
    const int g = lane >> 2, tig = lane & 3;

    const int arow = tid >> 2, ac4 = (tid & 3) * 4;   // 4 halves = 8B
    const int nrow = tid >> 1, kc8 = (tid & 1) * 8;

    float cg[2][4][4], cu[2][4][4];
    #pragma unroll
    for (int mf = 0; mf < 2; mf++)
        #pragma unroll
        for (int nf = 0; nf < 4; nf++)
            #pragma unroll
            for (int q = 0; q < 4; q++) { cg[mf][nf][q] = 0.f; cu[mf][nf][q] = 0.f; }

    auto issue = [&](int k0, int buf) {
        int k = k0 + ac4;
        const __half* src = (k < 128) ? &h[(long)(m0 + arow) * 128 + k]
                                      : &acc[(long)(m0 + arow) * 128 + (k - 128)];
        cp8(s2u(&As[buf][arow][ac4]), src);
        cp16(s2u(&BsG[buf][nrow][kc8]), &WgT[(long)nrow * 256 + k0 + kc8]);
        cp16(s2u(&BsU[buf][nrow][kc8]), &WuT[(long)nrow * 256 + k0 + kc8]);
        CP_COMMIT();
    };

    issue(0, 0);
    int buf = 0;
    for (int k0 = 0; k0 < 256; k0 += 16) {
        bool nxt = (k0 + 16) < 256;
        if (nxt) { issue(k0 + 16, buf ^ 1); CP_WAIT(1); }
        else     { CP_WAIT(0); }
        __syncthreads();
        uint32_t bgf[4][2], buf2[4][2];
        #pragma unroll
        for (int nf = 0; nf < 4; nf++) {
            int nc = n0w + nf * 8 + g;
            bgf[nf][0]  = *(const uint32_t*)&BsG[buf][nc][2 * tig];
            bgf[nf][1]  = *(const uint32_t*)&BsG[buf][nc][2 * tig + 8];
            buf2[nf][0] = *(const uint32_t*)&BsU[buf][nc][2 * tig];
            buf2[nf][1] = *(const uint32_t*)&BsU[buf][nc][2 * tig + 8];
        }
        #pragma unroll
        for (int mf = 0; mf < 2; mf++) {
            int mcol = m0w + mf * 16 + g;
            uint32_t a[4];
            a[0] = *(const uint32_t*)&As[buf][mcol    ][2 * tig];
            a[1] = *(const uint32_t*)&As[buf][mcol + 8][2 * tig];
            a[2] = *(const uint32_t*)&As[buf][mcol    ][2 * tig + 8];
            a[3] = *(const uint32_t*)&As[buf][mcol + 8][2 * tig + 8];
            #pragma unroll
            for (int nf = 0; nf < 4; nf++) {
                mma_f16(cg[mf][nf], a, bgf[nf]);
                mma_f16(cu[mf][nf], a, buf2[nf]);
            }
        }
        __syncthreads();
        buf ^= 1;
    }
    #pragma unroll
    for (int mf = 0; mf < 2; mf++) {
        int row0 = m0 + m0w + mf * 16 + g;
        #pragma unroll
        for (int nf = 0; nf < 4; nf++) {
            int col = n0w + nf * 8 + 2 * tig;
            float bg0 = bg[col], bg1 = bg[col + 1];
            float bu0 = bu[col], bu1 = bu[col + 1];
            float2 h0 = __half22float2(*(const __half2*)&h[(long)row0 * 128 + col]);
            float2 h1 = __half22float2(*(const __half2*)&h[(long)(row0 + 8) * 128 + col]);
            float G00 = tanhf(cg[mf][nf][0] + bg0), G01 = tanhf(cg[mf][nf][1] + bg1);
            float G10 = tanhf(cg[mf][nf][2] + bg0), G11 = tanhf(cg[mf][nf][3] + bg1);
            float U00 = tanhf(cu[mf][nf][0] + bu0), U01 = tanhf(cu[mf][nf][1] + bu1);
            float U10 = tanhf(cu[mf][nf][2] + bu0), U11 = tanhf(cu[mf][nf][3] + bu1);
            *(__half2*)&hout[(long)row0 * 128 + col] = __floats2half2_rn(
                G00 * U00 + (1.f - G00) * h0.x, G01 * U01 + (1.f - G01) * h0.y);
            *(__half2*)&hout[(long)(row0 + 8) * 128 + col] = __floats2half2_rn(
                G10 * U10 + (1.f - G10) * h1.x, G11 * U11 + (1.f - G11) * h1.y);
        }
    }
}

// ---------------- scalar fp32 GEMM (root layer) -> half out ------------------
__global__ void __launch_bounds__(256, 2) gemm_k(
    const float* __restrict__ A1, int lda1,
    const float* __restrict__ W,
    const float* __restrict__ bias,
    __half* __restrict__ C,
    int K, const float* __restrict__ pos)
{
    __shared__ float As[16][128];
    __shared__ float Bs[16][128];
    const int tid = threadIdx.x;
    const int m0  = blockIdx.x * 128;
    const int ty  = tid >> 4, tx = tid & 15;

    float acc[8][8];
    #pragma unroll
    for (int i = 0; i < 8; i++)
        #pragma unroll
        for (int j = 0; j < 8; j++) acc[i][j] = 0.f;

    for (int k0 = 0; k0 < K; k0 += 16) {
        #pragma unroll
        for (int i = 0; i < 2; i++) {
            int idx = tid + i * 256;
            int mr  = idx >> 2, c4 = (idx & 3) * 4;
            float4 v = *(const float4*)&A1[(long)(m0 + mr) * lda1 + k0 + c4];
            As[c4 + 0][mr] = v.x; As[c4 + 1][mr] = v.y;
            As[c4 + 2][mr] = v.z; As[c4 + 3][mr] = v.w;
        }
        #pragma unroll
        for (int i = 0; i < 2; i++) {
            int idx = tid + i * 256;
            int kr  = idx >> 5, c4 = (idx & 31) * 4;
            *(float4*)&Bs[kr][c4] = *(const float4*)&W[(long)(k0 + kr) * 128 + c4];
        }
        __syncthreads();
        #pragma unroll
        for (int kk = 0; kk < 16; kk++) {
            float a[8], b[8];
            #pragma unroll
            for (int i = 0; i < 8; i++) a[i] = As[kk][ty * 8 + i];
            #pragma unroll
            for (int j = 0; j < 8; j++) b[j] = Bs[kk][tx * 8 + j];
            #pragma unroll
            for (int i = 0; i < 8; i++)
                #pragma unroll
                for (int j = 0; j < 8; j++)
                    acc[i][j] += a[i] * b[j];
        }
        __syncthreads();
    }
    #pragma unroll
    for (int i = 0; i < 8; i++) {
        int gm = m0 + ty * 8 + i;
        #pragma unroll
        for (int j = 0; j < 8; j++) {
            int col = tx * 8 + j;
            float v = tanhf(acc[i][j] + bias[col]) + pos[(gm % N_) * 128 + col];
            C[(long)gm * 128 + col] = __float2half_rn(v);
        }
    }
}

// ---- merged preamble: Wf GEMMs (blocks 0-5, transposed half out), bias, hnum
__global__ void __launch_bounds__(256) pre_k(
    const float* __restrict__ Wq1, const float* __restrict__ Wk1,
    const float* __restrict__ Wv1, const float* __restrict__ Win,
    const float* __restrict__ bq1, const float* __restrict__ bk1,
    const float* __restrict__ bv1, const float* __restrict__ b_in,
    const float* __restrict__ num,
    const float* __restrict__ W0, const float* __restrict__ b0,
    const float* __restrict__ W1, const float* __restrict__ b1,
    __half* __restrict__ Wf, float* __restrict__ bf, float* __restrict__ hnum)
{
    __shared__ float sm[32 * 256 + 32 * 64];
    int tid = threadIdx.x;
    int blk = blockIdx.x;
    if (blk < 6) {
        int which = blk >> 1, tile = blk & 1;
        const float* A = (which == 0) ? Wq1 : (which == 1) ? Wk1 : Wv1;
        int wOff = which * 128;
        float* As = sm;
        float* Bs = sm + 2048;
        int m0 = tile * 128;
        int ty = tid >> 4, tx = tid & 15;
        float acc[8][8];
        #pragma unroll
        for (int i = 0; i < 8; i++)
            #pragma unroll
            for (int j = 0; j < 8; j++) acc[i][j] = 0.f;
        for (int k0 = 0; k0 < 128; k0 += 16) {
            #pragma unroll
            for (int i = 0; i < 2; i++) {
                int idx = tid + i * 256;
                int mr = idx >> 2, c4 = (idx & 3) * 4;
                float4 v = *(const float4*)&A[(long)(m0 + mr) * 128 + k0 + c4];
                As[(c4 + 0) * 128 + mr] = v.x; As[(c4 + 1) * 128 + mr] = v.y;
                As[(c4 + 2) * 128 + mr] = v.z; As[(c4 + 3) * 128 + mr] = v.w;
            }
            #pragma unroll
            for (int i = 0; i < 2; i++) {
                int idx = tid + i * 256;
                int kr = idx >> 5, c4 = (idx & 31) * 4;
                *(float4*)&Bs[kr * 128 + c4] = *(const float4*)&Win[(long)(k0 + kr) * 384 + wOff + c4];
            }
            __syncthreads();
            #pragma unroll
            for (int kk = 0; kk < 16; kk++) {
                float a[8], b[8];
                #pragma unroll
                for (int i = 0; i < 8; i++) a[i] = As[kk * 128 + ty * 8 + i];
                #pragma unroll
                for (int j = 0; j < 8; j++) b[j] = Bs[kk * 128 + tx * 8 + j];
                #pragma unroll
                for (int i = 0; i < 8; i++)
                    #pragma unroll
                    for (int j = 0; j < 8; j++)
                        acc[i][j] += a[i] * b[j];
            }
            __syncthreads();
        }
        // write transposed half: Wf[seg][n][k], k = row of Wq1 (0..255), n = col
        #pragma unroll
        for (int i = 0; i < 8; i++)
            #pragma unroll
            for (int j = 0; j < 8; j++)
                Wf[which * 32768 + (long)(tx * 8 + j) * 256 + (m0 + ty * 8 + i)] =
                    __float2half_rn(acc[i][j]);
    } else if (blk == 6) {
        float* sb = sm;
        for (int i = tid; i < 384; i += 256)
            sb[i] = (i < 128) ? bq1[i] : (i < 256) ? bk1[i - 128] : bv1[i - 256];
        __syncthreads();
        for (int col = tid; col < 384; col += 256) {
            float acc = b_in[col];
            int s = col >> 7;
            for (int k = 0; k < 128; k++)
                acc += sb[s * 128 + k] * Win[k * 384 + col];
            bf[col] = acc;
        }
    } else {
        float* sn = sm;
        float* sh = sm + 32 * 64;
        for (int i = tid; i < 32 * 64; i += 256) sn[i] = num[i];
        __syncthreads();
        for (int i = tid; i < 32 * 256; i += 256) {
            int r = i >> 8, c = i & 255;
            float a = b0[c];
            for (int k = 0; k < 64; k++) a += sn[r * 64 + k] * W0[k * 256 + c];
            sh[i] = tanhf(a);
        }
        __syncthreads();
        for (int i = tid; i < 32 * 128; i += 256) {
            int r = i >> 7, c = i & 127;
            float a = b1[c];
            for (int k = 0; k < 256; k++) a += sh[r * 256 + k] * W1[k * 128 + c];
            hnum[i] = tanhf(a);
        }
    }
}

// ---- build adjacency (fp16 atomics), both branches --------------------------
__global__ void __launch_bounds__(256) edgebuild2_k(
    const int* __restrict__ ei0, const int* __restrict__ ei1,
    __half* __restrict__ Abf)
{
    int gidx = blockIdx.x * 256 + threadIdx.x;
    int br = gidx / (B_ * E_);
    int e  = gidx % (B_ * E_);
    const int* ei = br ? ei1 : ei0;
    int b = e / E_;
    long base = (long)br * B_ * N_ * N_ + (long)b * N_ * N_;
    int e0 = ei[2 * e];
    int e1 = ei[2 * e + 1];
    __half one = __float2half(1.0f);
    atomicAdd(&Abf[base + (long)e0 * N_ + e1], one);
    atomicAdd(&Abf[base + (long)e1 * N_ + e0], one);
}

__global__ void zero_k(float* __restrict__ p, long n)
{
    long i = ((long)blockIdx.x * 256 + threadIdx.x) * 4;
    if (i < n) *(float4*)&p[i] = make_float4(0.f, 0.f, 0.f, 0.f);
}

// ---------------- attention: half in/out, fp32 internals ---------------------
__global__ void __launch_bounds__(256) attn2_k(
    const __half* __restrict__ q2,
    const __half* __restrict__ k2,
    const __half* __restrict__ v2,
    __half* __restrict__ oh)
{
    __shared__ float Ks[256][16];
    __shared__ float Vs[256][16];
    int qt = blockIdx.x, h = blockIdx.y, b = blockIdx.z;
    int tid = threadIdx.x;

    #pragma unroll
    for (int i = 0; i < 2; i++) {
        int idx = tid + i * 256;
        int j  = idx >> 1;
        int d8 = (idx & 1) * 8;
        uint4 kr = *(const uint4*)&k2[(long)(b * KB_ + j) * D_ + h * HD_ + d8];
        uint4 vr = *(const uint4*)&v2[(long)(b * KB_ + j) * D_ + h * HD_ + d8];
        const __half2* kp = (const __half2*)&kr;
        const __half2* vp = (const __half2*)&vr;
        #pragma unroll
        for (int t = 0; t < 4; t++) {
            float2 kf = __half22float2(kp[t]);
            float2 vf = __half22float2(vp[t]);
            Ks[j][d8 + 2*t] = kf.x; Ks[j][d8 + 2*t + 1] = kf.y;
            Vs[j][d8 + 2*t] = vf.x; Vs[j][d8 + 2*t + 1] = vf.y;
        }
    }
    __syncthreads();

    int qi = qt * 256 + tid;
    const __half* qp = &q2[(long)(b * N_ + qi) * D_ + h * HD_];
    float q[16];
    #pragma unroll
    for (int d = 0; d < 16; d += 2) {
        float2 f = __half22float2(*(const __half2*)&qp[d]);
        q[d] = f.x * 0.25f; q[d + 1] = f.y * 0.25f;
    }

    float m = -1e30f, sum = 0.f;
    float o[16];
    #pragma unroll
    for (int d = 0; d < 16; d++) o[d] = 0.f;

    for (int jj = 0; jj < 256; jj++) {
        float s = 0.f;
        float kreg[16];
        #pragma unroll
        for (int d4 = 0; d4 < 16; d4 += 4) {
            float4 kv = *(const float4*)&Ks[jj][d4];
            kreg[d4] = kv.x; kreg[d4+1] = kv.y; kreg[d4+2] = kv.z; kreg[d4+3] = kv.w;
        }
        #pragma unroll
        for (int d = 0; d < 16; d++) s = fmaf(q[d], kreg[d], s);
        float p;
        if (s > m) {
            float c = fexp(m - s);
            sum *= c;
            #pragma unroll
            for (int d = 0; d < 16; d++) o[d] *= c;
            m = s;
            p = 1.0f;
        } else {
            p = fexp(s - m);
        }
        sum += p;
        #pragma unroll
        for (int d4 = 0; d4 < 16; d4 += 4) {
            float4 vv = *(const float4*)&Vs[jj][d4];
            o[d4]   = fmaf(p, vv.x, o[d4]);
            o[d4+1] = fmaf(p, vv.y, o[d4+1]);
            o[d4+2] = fmaf(p, vv.z, o[d4+2]);
            o[d4+3] = fmaf(p, vv.w, o[d4+3]);
        }
    }
    float inv = 1.0f / sum;
    __half* op = &oh[(long)(b * N_ + qi) * D_ + h * HD_];
    #pragma unroll
    for (int d = 0; d < 16; d += 2)
        *(__half2*)&op[d] = __floats2half2_rn(o[d] * inv, o[d + 1] * inv);
}

// ---------------- mean + tail -------------------------------------------------
__global__ void mean1_k(const float* __restrict__ att, float* __restrict__ part)
{
    int b = blockIdx.x, ch = blockIdx.y, c = threadIdx.x;
    float s = 0.f;
    int n0 = ch * 128;
    for (int n = n0; n < n0 + 128; n++)
        s += att[(long)(b * N_ + n) * D_ + c];
    part[(b * 8 + ch) * 128 + c] = s;
}

__global__ void mean2_k(const float* __restrict__ part, float* __restrict__ hmean)
{
    int b = blockIdx.x, c = threadIdx.x;
    float s = 0.f;
    #pragma unroll
    for (int ch = 0; ch < 8; ch++)
        s += part[(b * 8 + ch) * 128 + c];
    hmean[b * 128 + c] = s * (1.0f / N_);
}

__global__ void tail_k(const float* __restrict__ hnum,
                       const float* __restrict__ hmean,
                       const float* __restrict__ stage,
                       float* __restrict__ out)
{
    int i = blockIdx.x * 256 + threadIdx.x;
    if (i < B_ * 258) {
        int b = i / 258, c = i % 258;
        float v = (c < 128) ? hnum[b * 128 + c]
                : (c < 256) ? hmean[b * 128 + (c - 128)]
                            : stage[b * 2 + (c - 256)];
        out[OFF_SV + i] = v;
    }
    if (i < M_) out[OFF_MK + i] = 1.0f;
    if (i < B_ * 2) out[OFF_ST + i] = stage[i];
}

// ---------------- launcher ----------------------------------------------------
extern "C" void kernel_launch(void* const* d_in, const int* in_sizes, int n_in,
                              void* d_out, int out_size)
{
    const float* numerical   = (const float*)d_in[0];
    const float* node_feat   = (const float*)d_in[1];
    const float* stage       = (const float*)d_in[2];
    const float* W_num0      = (const float*)d_in[3];
    const float* b_num0      = (const float*)d_in[4];
    const float* W_num1      = (const float*)d_in[5];
    const float* b_num1      = (const float*)d_in[6];
    const float* W_node      = (const float*)d_in[7];
    const float* b_node      = (const float*)d_in[8];
    const float* pos_enc     = (const float*)d_in[9];
    const float* ew1         = (const float*)d_in[10];
    const float* eb1         = (const float*)d_in[11];
    const float* ew2         = (const float*)d_in[12];
    const float* eb2         = (const float*)d_in[13];
    const float* Wg          = (const float*)d_in[14];
    const float* bg          = (const float*)d_in[15];
    const float* Wu          = (const float*)d_in[16];
    const float* bu          = (const float*)d_in[17];
    const float* Wq1         = (const float*)d_in[18];
    const float* bq1         = (const float*)d_in[19];
    const float* Wk1         = (const float*)d_in[20];
    const float* bk1         = (const float*)d_in[21];
    const float* Wv1         = (const float*)d_in[22];
    const float* bv1         = (const float*)d_in[23];
    const float* Win         = (const float*)d_in[24];
    const float* b_in        = (const float*)d_in[25];
    const float* Wout        = (const float*)d_in[26];
    const float* b_out       = (const float*)d_in[27];
    const int*   ei_dis      = (const int*)d_in[28];
    const int*   ei_od       = (const int*)d_in[29];
    const int*   build_idx   = (const int*)d_in[31];
    float* out = (float*)d_out;

    __half *p_h, *p_t, *p_fhb, *p_accb, *p_hb, *p_q2, *p_k2, *p_v2, *p_oh, *p_Wf, *p_Wr, *p_Abf;
    float *p_hnum, *p_hmean, *p_part, *p_bf;
    cudaGetSymbolAddress((void**)&p_h,    g_h);
    cudaGetSymbolAddress((void**)&p_t,    g_t);
    cudaGetSymbolAddress((void**)&p_fhb,  g_fhb);
    cudaGetSymbolAddress((void**)&p_accb, g_accb);
    cudaGetSymbolAddress((void**)&p_hb,   g_hb);
    cudaGetSymbolAddress((void**)&p_q2,   g_q2);
    cudaGetSymbolAddress((void**)&p_k2,   g_k2);
    cudaGetSymbolAddress((void**)&p_v2,   g_v2);
    cudaGetSymbolAddress((void**)&p_oh,   g_oh);
    cudaGetSymbolAddress((void**)&p_hnum, g_hnum);
    cudaGetSymbolAddress((void**)&p_hmean,g_hmean);
    cudaGetSymbolAddress((void**)&p_part, g_part);
    cudaGetSymbolAddress((void**)&p_Wf,   g_Wf);
    cudaGetSymbolAddress((void**)&p_bf,   g_bf);
    cudaGetSymbolAddress((void**)&p_Wr,   g_Wr);
    cudaGetSymbolAddress((void**)&p_Abf,  g_Abf);

    // preamble + weight round/transpose
    pre_k<<<8, 256>>>(Wq1, Wk1, Wv1, Win, bq1, bk1, bv1, b_in,
                      numerical, W_num0, b_num0, W_num1, b_num1,
                      p_Wf, p_bf, p_hnum);
    round_k<<<WR_TOT / 256, 256>>>(ew1, ew2, Wg, Wu, Wout, p_Wr);

    // h = tanh(node_feature @ W_node + b_node) + pos_enc -> half
    gemm_k<<<256, 256>>>(node_feat, 32, W_node, b_node, p_h, 32, pos_enc);

    // zero adjacency (fp16, both branches: 134MB)
    zero_k<<<(int)((2L*B_*N_*N_/2)/1024), 256>>>((float*)p_Abf, 2L*B_*N_*N_/2);

    // edge MLPs, both branches batched per stage
    tgemm2h_k<<<dim3(256, 2), 256>>>(p_h, p_h,
                                     p_Wr + WR_E1L0, p_Wr + WR_E2L0,
                                     eb1 + 256, eb2 + 256,
                                     p_t, p_t + M_*D_, 1, 0);
    tgemm2h_k<<<dim3(256, 2), 256>>>(p_t, p_t + M_*D_,
                                     p_Wr + WR_E1L1, p_Wr + WR_E2L1,
                                     eb1 + 384, eb2 + 384,
                                     p_fhb, p_fhb + M_*D_, 1, 0);

    // build + aggregate (deg in-kernel; acc scaled)
    edgebuild2_k<<<2*B_*E_/256, 256>>>(ei_dis, ei_od, p_Abf);
    adjh_k<<<dim3(8, 32, 2), 256>>>(p_Abf, p_fhb, p_accb);

    // fused gate+update+combine
    guh_k<<<dim3(M_/64, 2), 256>>>(p_h, p_accb, p_Wr + WR_WG, bg, p_Wr + WR_WU, bu, p_hb);

    // q2/k2/v2 in one launch
    qkvh_k<<<384, 256>>>(p_hb, p_hb + M_*D_, build_idx, p_Wf, p_bf, p_q2, p_k2, p_v2);

    // attention
    attn2_k<<<dim3(4, H_, B_), 256>>>(p_q2, p_k2, p_v2, p_oh);

    // h_att = oh @ W_out + b_out -> fp32 final output
    tgemm2h_k<<<dim3(256, 1), 256>>>(p_oh, p_oh,
                                     p_Wr + WR_WOUT, p_Wr + WR_WOUT,
                                     b_out, b_out, out, out, 0, 1);

    // mean + tail
    mean1_k<<<dim3(32, 8), 128>>>(out, p_part);
    mean2_k<<<32, 128>>>(p_part, p_hmean);
    tail_k<<<129, 256>>>(p_hnum, p_hmean, stage, out);

    (void)in_sizes; (void)n_in; (void)out_size;
}

// round 16
// speedup vs baseline: 1.0589x; 1.0589x over previous
#include <cuda_runtime.h>
#include <cuda_bf16.h>
#include <math.h>
#include <stdint.h>

// Problem constants
#define B_   32
#define N_   1024
#define E_   16384
#define D_   128
#define M_   (B_*N_)      // 32768
#define KB_  256
#define H_   8
#define HD_  16
#define EPSF 1e-6f

#define OFF_SV (M_*D_)
#define OFF_MK (OFF_SV + B_*258)
#define OFF_ST (OFF_MK + M_)

// rounded-weight scratch offsets (floats)
#define WR_E1L0 0
#define WR_E1L1 16384
#define WR_E2L0 32768
#define WR_E2L1 49152
#define WR_WG   65536
#define WR_WU   98304
#define WR_WOUT 131072
#define WR_TOT  147456

// ---------------- scratch ----------------
__device__ float g_h   [M_*D_];
__device__ float g_t   [2*M_*D_];
__device__ float g_fhb [2*M_*D_];
__device__ float g_accb[2*M_*D_];   // pre-scaled by 1/(deg+eps), tf32-rounded
__device__ float g_hb  [2*M_*D_];
__device__ float g_q2  [M_*D_];
__device__ float g_k2  [B_*KB_*D_];
__device__ float g_v2  [B_*KB_*D_];
__device__ float g_oh  [M_*D_];
__device__ float g_hnum [B_*128];
__device__ float g_hmean[B_*128];
__device__ float g_part [B_*8*128];
__device__ float g_Wf  [3*256*128];
__device__ float g_bf  [3*128];
__device__ float g_Wr  [WR_TOT];
__device__ __nv_bfloat16 g_Abf[2L*B_*N_*N_];   // adjacency counts (134MB)

// ---------------- helpers ----------------
__device__ __forceinline__ float to_tf32(float x) {
    uint32_t u;
    asm("cvt.rna.tf32.f32 %0, %1;" : "=r"(u) : "f"(x));
    return __uint_as_float(u);
}

__device__ __forceinline__ void mma_tf32(float c[4], const uint32_t a[4], const uint32_t b[2]) {
    asm volatile(
        "mma.sync.aligned.m16n8k8.row.col.f32.tf32.tf32.f32 "
        "{%0,%1,%2,%3}, {%4,%5,%6,%7}, {%8,%9}, {%0,%1,%2,%3};"
        : "+f"(c[0]), "+f"(c[1]), "+f"(c[2]), "+f"(c[3])
        : "r"(a[0]), "r"(a[1]), "r"(a[2]), "r"(a[3]), "r"(b[0]), "r"(b[1]));
}

__device__ __forceinline__ void cp16(uint32_t dst, const void* src) {
    asm volatile("cp.async.ca.shared.global [%0], [%1], 16;" :: "r"(dst), "l"(src));
}
__device__ __forceinline__ uint32_t s2u(const void* p) {
    return (uint32_t)__cvta_generic_to_shared(p);
}
#define CP_COMMIT() asm volatile("cp.async.commit_group;")
#define CP_WAIT(n)  asm volatile("cp.async.wait_group %0;" :: "n"(n))

// fast exp on FMA pipe
__device__ __forceinline__ float fexp(float x) {
    x = fmaxf(x, -87.0f);
    float t = x * 1.4426950408889634f;
    float fn = rintf(t);
    float f = t - fn;
    float p = 1.3333558146e-3f;
    p = fmaf(p, f, 9.6179662376e-3f);
    p = fmaf(p, f, 5.5490420128e-2f);
    p = fmaf(p, f, 2.4022650696e-1f);
    p = fmaf(p, f, 6.9314718056e-1f);
    p = fmaf(p, f, 1.0f);
    int n = (int)fn;
    float sc = __int_as_float((n + 127) << 23);
    return p * sc;
}

// ---- round input weights (RNA) into scratch ---------------------------------
__global__ void round_k(const float* __restrict__ ew1, const float* __restrict__ ew2,
                        const float* __restrict__ Wg,  const float* __restrict__ Wu,
                        const float* __restrict__ Wout, float* __restrict__ Wr)
{
    int i = blockIdx.x * 256 + threadIdx.x;   // 576 * 256 = 147456
    float v;
    if      (i < 16384)  v = ew1[32768 + i];
    else if (i < 32768)  v = ew1[49152 + (i - 16384)];
    else if (i < 49152)  v = ew2[32768 + (i - 32768)];
    else if (i < 65536)  v = ew2[49152 + (i - 49152)];
    else if (i < 98304)  v = Wg[i - 65536];
    else if (i < 131072) v = Wu[i - 98304];
    else                 v = Wout[i - 131072];
    Wr[i] = to_tf32(v);
}

// ------- tf32 GEMM (K=128), cp.async double-buffer, dual-branch --------------
__global__ void __launch_bounds__(256, 2) tgemm2_k(
    const float* __restrict__ A0p, const float* __restrict__ A1p,
    const float* __restrict__ W0p, const float* __restrict__ W1p,
    const float* __restrict__ b0p, const float* __restrict__ b1p,
    float* __restrict__ C0p, float* __restrict__ C1p,
    int epi, int rnd)
{
    const int br = blockIdx.y;
    const float* A    = br ? A1p : A0p;
    const float* W    = br ? W1p : W0p;
    const float* bias = br ? b1p : b0p;
    float*       C    = br ? C1p : C0p;

    __shared__ float As[2][128][20];
    __shared__ float Bs[2][16][136];
    const int tid = threadIdx.x;
    const int m0  = blockIdx.x * 128;
    const int warp = tid >> 5, lane = tid & 31;
    const int m0w = (warp >> 2) * 64, n0w = (warp & 3) * 32;
    const int g = lane >> 2, tig = lane & 3;

    const int arow = tid >> 1, ac8 = (tid & 1) * 8;
    const int brow = tid >> 4, bc8 = (tid & 15) * 8;
    const long abase = (long)(m0 + arow) * 128;

    float c[4][4][4];
    #pragma unroll
    for (int mf = 0; mf < 4; mf++)
        #pragma unroll
        for (int nf = 0; nf < 4; nf++)
            #pragma unroll
            for (int q = 0; q < 4; q++) c[mf][nf][q] = 0.f;

    #pragma unroll
    for (int j = 0; j < 2; j++) {
        cp16(s2u(&As[0][arow][ac8 + j * 4]), &A[abase + ac8 + j * 4]);
        cp16(s2u(&Bs[0][brow][bc8 + j * 4]), &W[(long)brow * 128 + bc8 + j * 4]);
    }
    CP_COMMIT();

    int buf = 0;
    for (int k0 = 0; k0 < 128; k0 += 16) {
        bool nxt = (k0 + 16) < 128;
        if (nxt) {
            int kn = k0 + 16;
            #pragma unroll
            for (int j = 0; j < 2; j++) {
                cp16(s2u(&As[buf ^ 1][arow][ac8 + j * 4]), &A[abase + kn + ac8 + j * 4]);
                cp16(s2u(&Bs[buf ^ 1][brow][bc8 + j * 4]), &W[(long)(kn + brow) * 128 + bc8 + j * 4]);
            }
            CP_COMMIT();
            CP_WAIT(1);
        } else CP_WAIT(0);
        __syncthreads();
        #pragma unroll
        for (int kk = 0; kk < 2; kk++) {
            int kb = kk * 8;
            uint32_t b[4][2];
            #pragma unroll
            for (int nf = 0; nf < 4; nf++) {
                int nc = n0w + nf * 8 + g;
                b[nf][0] = __float_as_uint(Bs[buf][kb + tig    ][nc]);
                b[nf][1] = __float_as_uint(Bs[buf][kb + tig + 4][nc]);
            }
            #pragma unroll
            for (int mf = 0; mf < 4; mf++) {
                int mcol = m0w + mf * 16 + g;
                uint32_t a[4];
                a[0] = __float_as_uint(As[buf][mcol    ][kb + tig]);
                a[1] = __float_as_uint(As[buf][mcol + 8][kb + tig]);
                a[2] = __float_as_uint(As[buf][mcol    ][kb + tig + 4]);
                a[3] = __float_as_uint(As[buf][mcol + 8][kb + tig + 4]);
                #pragma unroll
                for (int nf = 0; nf < 4; nf++)
                    mma_tf32(c[mf][nf], a, b[nf]);
            }
        }
        __syncthreads();
        buf ^= 1;
    }
    #pragma unroll
    for (int mf = 0; mf < 4; mf++) {
        int row0 = m0 + m0w + mf * 16 + g;
        #pragma unroll
        for (int nf = 0; nf < 4; nf++) {
            int col = n0w + nf * 8 + 2 * tig;
            float b0 = bias[col], b1 = bias[col + 1];
            float v00 = c[mf][nf][0] + b0, v01 = c[mf][nf][1] + b1;
            float v10 = c[mf][nf][2] + b0, v11 = c[mf][nf][3] + b1;
            if (epi == 1) { v00 = tanhf(v00); v01 = tanhf(v01); v10 = tanhf(v10); v11 = tanhf(v11); }
            if (rnd) { v00 = to_tf32(v00); v01 = to_tf32(v01); v10 = to_tf32(v10); v11 = to_tf32(v11); }
            *(float2*)&C[(long)row0 * 128 + col]       = make_float2(v00, v01);
            *(float2*)&C[(long)(row0 + 8) * 128 + col] = make_float2(v10, v11);
        }
    }
}

// ---- q2/k2/v2 merged GEMM (K=256 concat hb0|hb1), 384 blocks ----------------
__global__ void __launch_bounds__(256, 2) qkv_k(
    const float* __restrict__ hb0, const float* __restrict__ hb1,
    const int* __restrict__ bidx,
    const float* __restrict__ Wf, const float* __restrict__ bf,
    float* __restrict__ q2, float* __restrict__ k2, float* __restrict__ v2)
{
    const int x = blockIdx.x;
    const int seg = (x < 256) ? 0 : (x < 320 ? 1 : 2);
    const int mb  = (seg == 0) ? x : (seg == 1 ? x - 256 : x - 320);
    const int m0  = mb * 128;
    const float* W    = Wf + seg * 32768;
    const float* bias = bf + seg * 128;
    float* C = (seg == 0) ? q2 : (seg == 1 ? k2 : v2);

    __shared__ float As[2][128][20];
    __shared__ float Bs[2][16][136];
    const int tid = threadIdx.x;
    const int warp = tid >> 5, lane = tid & 31;
    const int m0w = (warp >> 2) * 64, n0w = (warp & 3) * 32;
    const int g = lane >> 2, tig = lane & 3;

    const int arow = tid >> 1, ac8 = (tid & 1) * 8;
    const int brow = tid >> 4, bc8 = (tid & 15) * 8;
    int pr;
    { int gm = m0 + arow; pr = (seg == 0) ? gm : (gm / KB_) * N_ + bidx[gm % KB_]; }
    const long abase = (long)pr * 128;

    float c[4][4][4];
    #pragma unroll
    for (int mf = 0; mf < 4; mf++)
        #pragma unroll
        for (int nf = 0; nf < 4; nf++)
            #pragma unroll
            for (int q = 0; q < 4; q++) c[mf][nf][q] = 0.f;

    auto asrc = [&](int k) -> const float* {
        return (k < 128) ? &hb0[abase + k] : &hb1[abase + (k - 128)];
    };

    #pragma unroll
    for (int j = 0; j < 2; j++) {
        cp16(s2u(&As[0][arow][ac8 + j * 4]), asrc(ac8 + j * 4));
        cp16(s2u(&Bs[0][brow][bc8 + j * 4]), &W[(long)brow * 128 + bc8 + j * 4]);
    }
    CP_COMMIT();

    int buf = 0;
    for (int k0 = 0; k0 < 256; k0 += 16) {
        bool nxt = (k0 + 16) < 256;
        if (nxt) {
            int kn = k0 + 16;
            #pragma unroll
            for (int j = 0; j < 2; j++) {
                cp16(s2u(&As[buf ^ 1][arow][ac8 + j * 4]), asrc(kn + ac8 + j * 4));
                cp16(s2u(&Bs[buf ^ 1][brow][bc8 + j * 4]), &W[(long)(kn + brow) * 128 + bc8 + j * 4]);
            }
            CP_COMMIT();
            CP_WAIT(1);
        } else CP_WAIT(0);
        __syncthreads();
        #pragma unroll
        for (int kk = 0; kk < 2; kk++) {
            int kb = kk * 8;
            uint32_t b[4][2];
            #pragma unroll
            for (int nf = 0; nf < 4; nf++) {
                int nc = n0w + nf * 8 + g;
                b[nf][0] = __float_as_uint(Bs[buf][kb + tig    ][nc]);
                b[nf][1] = __float_as_uint(Bs[buf][kb + tig + 4][nc]);
            }
            #pragma unroll
            for (int mf = 0; mf < 4; mf++) {
                int mcol = m0w + mf * 16 + g;
                uint32_t a[4];
                a[0] = __float_as_uint(As[buf][mcol    ][kb + tig]);
                a[1] = __float_as_uint(As[buf][mcol + 8][kb + tig]);
                a[2] = __float_as_uint(As[buf][mcol    ][kb + tig + 4]);
                a[3] = __float_as_uint(As[buf][mcol + 8][kb + tig + 4]);
                #pragma unroll
                for (int nf = 0; nf < 4; nf++)
                    mma_tf32(c[mf][nf], a, b[nf]);
            }
        }
        __syncthreads();
        buf ^= 1;
    }
    #pragma unroll
    for (int mf = 0; mf < 4; mf++) {
        int row0 = m0 + m0w + mf * 16 + g;
        #pragma unroll
        for (int nf = 0; nf < 4; nf++) {
            int col = n0w + nf * 8 + 2 * tig;
            float b0 = bias[col], b1 = bias[col + 1];
            *(float2*)&C[(long)row0 * 128 + col] =
                make_float2(to_tf32(c[mf][nf][0] + b0), to_tf32(c[mf][nf][1] + b1));
            *(float2*)&C[(long)(row0 + 8) * 128 + col] =
                make_float2(to_tf32(c[mf][nf][2] + b0), to_tf32(c[mf][nf][3] + b1));
        }
    }
}

// ---- adjacency aggregation, bf16 A; deg via fragment rowsum; scaled+rounded -
__global__ void __launch_bounds__(256, 2) adj_tgemm_k(
    const __nv_bfloat16* __restrict__ Abf,
    const float* __restrict__ fhb,
    float* __restrict__ accb)
{
    __shared__ float As[2][128][20];
    __shared__ float Bs[2][16][136];
    __shared__ float degS[128];
    const int tid = threadIdx.x;
    const int bb = blockIdx.y, br = blockIdx.z;
    const int m0 = blockIdx.x * 128;
    const int warp = tid >> 5, lane = tid & 31;
    const int m0w = (warp >> 2) * 64, n0w = (warp & 3) * 32;
    const int g = lane >> 2, tig = lane & 3;
    const __nv_bfloat16* Ab = Abf + (long)br * B_ * N_ * N_ + (long)bb * N_ * N_;
    const float* fhp = fhb + (long)br * M_ * D_ + (long)bb * N_ * D_;
    float* accp = accb + (long)br * M_ * D_;

    const int arow = tid >> 1, ac8 = (tid & 1) * 8;
    const int brow = tid >> 4, bc8 = (tid & 15) * 8;

    float c[4][4][4];
    float ds0[4], ds1[4];
    #pragma unroll
    for (int mf = 0; mf < 4; mf++) {
        ds0[mf] = 0.f; ds1[mf] = 0.f;
        #pragma unroll
        for (int nf = 0; nf < 4; nf++)
            #pragma unroll
            for (int q = 0; q < 4; q++) c[mf][nf][q] = 0.f;
    }

    auto cvt_store = [&](int buf, uint4 raw) {
        const __nv_bfloat162* p2 = (const __nv_bfloat162*)&raw;
        #pragma unroll
        for (int j = 0; j < 4; j++) {
            float2 f = __bfloat1622float2(p2[j]);
            As[buf][arow][ac8 + 2 * j]     = f.x;
            As[buf][arow][ac8 + 2 * j + 1] = f.y;
        }
    };

    uint4 r0 = *(const uint4*)(Ab + (long)(m0 + arow) * N_ + ac8);
    #pragma unroll
    for (int j = 0; j < 2; j++)
        cp16(s2u(&Bs[0][brow][bc8 + j * 4]), &fhp[(long)brow * D_ + bc8 + j * 4]);
    CP_COMMIT();
    cvt_store(0, r0);

    int buf = 0;
    for (int k0 = 0; k0 < N_; k0 += 16) {
        bool nxt = (k0 + 16) < N_;
        uint4 r2;
        if (nxt) {
            int kn = k0 + 16;
            r2 = *(const uint4*)(Ab + (long)(m0 + arow) * N_ + kn + ac8);
            #pragma unroll
            for (int j = 0; j < 2; j++)
                cp16(s2u(&Bs[buf ^ 1][brow][bc8 + j * 4]),
                     &fhp[(long)(kn + brow) * D_ + bc8 + j * 4]);
            CP_COMMIT();
            CP_WAIT(1);
        } else CP_WAIT(0);
        __syncthreads();
        #pragma unroll
        for (int kk = 0; kk < 2; kk++) {
            int kb = kk * 8;
            uint32_t b[4][2];
            #pragma unroll
            for (int nf = 0; nf < 4; nf++) {
                int nc = n0w + nf * 8 + g;
                b[nf][0] = __float_as_uint(Bs[buf][kb + tig    ][nc]);
                b[nf][1] = __float_as_uint(Bs[buf][kb + tig + 4][nc]);
            }
            #pragma unroll
            for (int mf = 0; mf < 4; mf++) {
                int mcol = m0w + mf * 16 + g;
                uint32_t a[4];
                a[0] = __float_as_uint(As[buf][mcol    ][kb + tig]);
                a[1] = __float_as_uint(As[buf][mcol + 8][kb + tig]);
                a[2] = __float_as_uint(As[buf][mcol    ][kb + tig + 4]);
                a[3] = __float_as_uint(As[buf][mcol + 8][kb + tig + 4]);
                ds0[mf] += __uint_as_float(a[0]) + __uint_as_float(a[2]);
                ds1[mf] += __uint_as_float(a[1]) + __uint_as_float(a[3]);
                #pragma unroll
                for (int nf = 0; nf < 4; nf++)
                    mma_tf32(c[mf][nf], a, b[nf]);
            }
        }
        if (nxt) cvt_store(buf ^ 1, r2);
        __syncthreads();
        buf ^= 1;
    }
    #pragma unroll
    for (int mf = 0; mf < 4; mf++) {
        float d0 = ds0[mf], d1 = ds1[mf];
        d0 += __shfl_xor_sync(0xffffffffu, d0, 1);
        d0 += __shfl_xor_sync(0xffffffffu, d0, 2);
        d1 += __shfl_xor_sync(0xffffffffu, d1, 1);
        d1 += __shfl_xor_sync(0xffffffffu, d1, 2);
        if ((warp & 3) == 0 && tig == 0) {
            degS[m0w + mf * 16 + g]     = d0;
            degS[m0w + mf * 16 + g + 8] = d1;
        }
    }
    __syncthreads();
    #pragma unroll
    for (int mf = 0; mf < 4; mf++) {
        int rowl = m0w + mf * 16 + g;
        int row0 = bb * N_ + m0 + rowl;
        float s0 = 1.0f / (degS[rowl] + EPSF);
        float s1 = 1.0f / (degS[rowl + 8] + EPSF);
        #pragma unroll
        for (int nf = 0; nf < 4; nf++) {
            int col = n0w + nf * 8 + 2 * tig;
            *(float2*)&accp[(long)row0 * 128 + col] =
                make_float2(to_tf32(c[mf][nf][0] * s0), to_tf32(c[mf][nf][1] * s0));
            *(float2*)&accp[(long)(row0 + 8) * 128 + col] =
                make_float2(to_tf32(c[mf][nf][2] * s1), to_tf32(c[mf][nf][3] * s1));
        }
    }
}

// ---- fused gate+update+combine dual GEMM ------------------------------------
__global__ void __launch_bounds__(256, 2) gu_k(
    const float* __restrict__ h,
    const float* __restrict__ accb,
    const float* __restrict__ Wg, const float* __restrict__ bg,
    const float* __restrict__ Wu, const float* __restrict__ bu,
    float* __restrict__ houtb)
{
    const int br = blockIdx.y;
    const float* acc = accb + (long)br * M_ * D_;
    float* hout = houtb + (long)br * M_ * D_;

    __shared__ float As [2][64][20];
    __shared__ float BsG[2][16][136];
    __shared__ float BsU[2][16][136];
    const int tid = threadIdx.x;
    const int m0 = blockIdx.x * 64;
    const int warp = tid >> 5, lane = tid & 31;
    const int m0w = (warp >> 2) * 32, n0w = (warp & 3) * 32;
    const int g = lane >> 2, tig = lane & 3;

    const int arow = tid >> 2, ac4 = (tid & 3) * 4;
    const int brow = tid >> 4, bc8 = (tid & 15) * 8;

    float cg[2][4][4], cu[2][4][4];
    #pragma unroll
    for (int mf = 0; mf < 2; mf++)
        #pragma unroll
        for (int nf = 0; nf < 4; nf++)
            #pragma unroll
            for (int q = 0; q < 4; q++) { cg[mf][nf][q] = 0.f; cu[mf][nf][q] = 0.f; }

    auto issue = [&](int k0, int buf) {
        int k = k0 + ac4;
        const float* src = (k < 128) ? &h[(long)(m0 + arow) * 128 + k]
                                     : &acc[(long)(m0 + arow) * 128 + (k - 128)];
        cp16(s2u(&As[buf][arow][ac4]), src);
        #pragma unroll
        for (int j = 0; j < 2; j++) {
            cp16(s2u(&BsG[buf][brow][bc8 + j * 4]), &Wg[(long)(k0 + brow) * 128 + bc8 + j * 4]);
            cp16(s2u(&BsU[buf][brow][bc8 + j * 4]), &Wu[(long)(k0 + brow) * 128 + bc8 + j * 4]);
        }
        CP_COMMIT();
    };

    issue(0, 0);
    int buf = 0;
    for (int k0 = 0; k0 < 256; k0 += 16) {
        bool nxt = (k0 + 16) < 256;
        if (nxt) { issue(k0 + 16, buf ^ 1); CP_WAIT(1); }
        else     { CP_WAIT(0); }
        __syncthreads();
        #pragma unroll
        for (int kk = 0; kk < 2; kk++) {
            int kb = kk * 8;
            uint32_t bgf[4][2], buf2[4][2];
            #pragma unroll
            for (int nf = 0; nf < 4; nf++) {
                int nc = n0w + nf * 8 + g;
                bgf[nf][0]  = __float_as_uint(BsG[buf][kb + tig    ][nc]);
                bgf[nf][1]  = __float_as_uint(BsG[buf][kb + tig + 4][nc]);
                buf2[nf][0] = __float_as_uint(BsU[buf][kb + tig    ][nc]);
                buf2[nf][1] = __float_as_uint(BsU[buf][kb + tig + 4][nc]);
            }
            #pragma unroll
            for (int mf = 0; mf < 2; mf++) {
                int mcol = m0w + mf * 16 + g;
                uint32_t a[4];
                a[0] = __float_as_uint(As[buf][mcol    ][kb + tig]);
                a[1] = __float_as_uint(As[buf][mcol + 8][kb + tig]);
                a[2] = __float_as_uint(As[buf][mcol    ][kb + tig + 4]);
                a[3] = __float_as_uint(As[buf][mcol + 8][kb + tig + 4]);
                #pragma unroll
                for (int nf = 0; nf < 4; nf++) {
                    mma_tf32(cg[mf][nf], a, bgf[nf]);
                    mma_tf32(cu[mf][nf], a, buf2[nf]);
                }
            }
        }
        __syncthreads();
        buf ^= 1;
    }
    #pragma unroll
    for (int mf = 0; mf < 2; mf++) {
        int row0 = m0 + m0w + mf * 16 + g;
        #pragma unroll
        for (int nf = 0; nf < 4; nf++) {
            int col = n0w + nf * 8 + 2 * tig;
            float bg0 = bg[col], bg1 = bg[col + 1];
            float bu0 = bu[col], bu1 = bu[col + 1];
            float2 h0 = *(const float2*)&h[(long)row0 * 128 + col];
            float2 h1 = *(const float2*)&h[(long)(row0 + 8) * 128 + col];
            float G00 = tanhf(cg[mf][nf][0] + bg0), G01 = tanhf(cg[mf][nf][1] + bg1);
            float G10 = tanhf(cg[mf][nf][2] + bg0), G11 = tanhf(cg[mf][nf][3] + bg1);
            float U00 = tanhf(cu[mf][nf][0] + bu0), U01 = tanhf(cu[mf][nf][1] + bu1);
            float U10 = tanhf(cu[mf][nf][2] + bu0), U11 = tanhf(cu[mf][nf][3] + bu1);
            *(float2*)&hout[(long)row0 * 128 + col] = make_float2(
                to_tf32(G00 * U00 + (1.f - G00) * h0.x),
                to_tf32(G01 * U01 + (1.f - G01) * h0.y));
            *(float2*)&hout[(long)(row0 + 8) * 128 + col] = make_float2(
                to_tf32(G10 * U10 + (1.f - G10) * h1.x),
                to_tf32(G11 * U11 + (1.f - G11) * h1.y));
        }
    }
}

// ---------------- scalar fp32 GEMM (root layer) ------------------------------
__global__ void __launch_bounds__(256, 2) gemm_k(
    const float* __restrict__ A1, int lda1,
    const float* __restrict__ W, int ldw, int wOff,
    const float* __restrict__ bias,
    float* __restrict__ C,
    int K, int epi, const float* __restrict__ pos)
{
    __shared__ float As[16][128];
    __shared__ float Bs[16][128];
    const int tid = threadIdx.x;
    const int m0  = blockIdx.x * 128;
    const int ty  = tid >> 4, tx = tid & 15;

    float acc[8][8];
    #pragma unroll
    for (int i = 0; i < 8; i++)
        #pragma unroll
        for (int j = 0; j < 8; j++) acc[i][j] = 0.f;

    for (int k0 = 0; k0 < K; k0 += 16) {
        #pragma unroll
        for (int i = 0; i < 2; i++) {
            int idx = tid + i * 256;
            int mr  = idx >> 2, c4 = (idx & 3) * 4;
            float4 v = *(const float4*)&A1[(long)(m0 + mr) * lda1 + k0 + c4];
            As[c4 + 0][mr] = v.x; As[c4 + 1][mr] = v.y;
            As[c4 + 2][mr] = v.z; As[c4 + 3][mr] = v.w;
        }
        #pragma unroll
        for (int i = 0; i < 2; i++) {
            int idx = tid + i * 256;
            int kr  = idx >> 5, c4 = (idx & 31) * 4;
            *(float4*)&Bs[kr][c4] = *(const float4*)&W[(long)(k0 + kr) * ldw + wOff + c4];
        }
        __syncthreads();
        #pragma unroll
        for (int kk = 0; kk < 16; kk++) {
            float a[8], b[8];
            #pragma unroll
            for (int i = 0; i < 8; i++) a[i] = As[kk][ty * 8 + i];
            #pragma unroll
            for (int j = 0; j < 8; j++) b[j] = Bs[kk][tx * 8 + j];
            #pragma unroll
            for (int i = 0; i < 8; i++)
                #pragma unroll
                for (int j = 0; j < 8; j++)
                    acc[i][j] += a[i] * b[j];
        }
        __syncthreads();
    }
    #pragma unroll
    for (int i = 0; i < 8; i++) {
        int gm = m0 + ty * 8 + i;
        #pragma unroll
        for (int j = 0; j < 8; j++) {
            int col = tx * 8 + j;
            float v = acc[i][j] + bias[col];
            if (epi >= 1) v = tanhf(v);
            if (epi == 2) { v += pos[(gm % N_) * 128 + col]; v = to_tf32(v); }
            C[(long)gm * 128 + col] = v;
        }
    }
}

// ---- merged preamble: Wf GEMMs (blocks 0-5), fused bias (6), hnum (7) -------
__global__ void __launch_bounds__(256) pre_k(
    const float* __restrict__ Wq1, const float* __restrict__ Wk1,
    const float* __restrict__ Wv1, const float* __restrict__ Win,
    const float* __restrict__ bq1, const float* __restrict__ bk1,
    const float* __restrict__ bv1, const float* __restrict__ b_in,
    const float* __restrict__ num,
    const float* __restrict__ W0, const float* __restrict__ b0,
    const float* __restrict__ W1, const float* __restrict__ b1,
    float* __restrict__ Wf, float* __restrict__ bf, float* __restrict__ hnum)
{
    __shared__ float sm[32 * 256 + 32 * 64];
    int tid = threadIdx.x;
    int blk = blockIdx.x;
    if (blk < 6) {
        int which = blk >> 1, tile = blk & 1;
        const float* A = (which == 0) ? Wq1 : (which == 1) ? Wk1 : Wv1;
        int wOff = which * 128;
        float* As = sm;
        float* Bs = sm + 2048;
        int m0 = tile * 128;
        int ty = tid >> 4, tx = tid & 15;
        float acc[8][8];
        #pragma unroll
        for (int i = 0; i < 8; i++)
            #pragma unroll
            for (int j = 0; j < 8; j++) acc[i][j] = 0.f;
        for (int k0 = 0; k0 < 128; k0 += 16) {
            #pragma unroll
            for (int i = 0; i < 2; i++) {
                int idx = tid + i * 256;
                int mr = idx >> 2, c4 = (idx & 3) * 4;
                float4 v = *(const float4*)&A[(long)(m0 + mr) * 128 + k0 + c4];
                As[(c4 + 0) * 128 + mr] = v.x; As[(c4 + 1) * 128 + mr] = v.y;
                As[(c4 + 2) * 128 + mr] = v.z; As[(c4 + 3) * 128 + mr] = v.w;
            }
            #pragma unroll
            for (int i = 0; i < 2; i++) {
                int idx = tid + i * 256;
                int kr = idx >> 5, c4 = (idx & 31) * 4;
                *(float4*)&Bs[kr * 128 + c4] = *(const float4*)&Win[(long)(k0 + kr) * 384 + wOff + c4];
            }
            __syncthreads();
            #pragma unroll
            for (int kk = 0; kk < 16; kk++) {
                float a[8], b[8];
                #pragma unroll
                for (int i = 0; i < 8; i++) a[i] = As[kk * 128 + ty * 8 + i];
                #pragma unroll
                for (int j = 0; j < 8; j++) b[j] = Bs[kk * 128 + tx * 8 + j];
                #pragma unroll
                for (int i = 0; i < 8; i++)
                    #pragma unroll
                    for (int j = 0; j < 8; j++)
                        acc[i][j] += a[i] * b[j];
            }
            __syncthreads();
        }
        #pragma unroll
        for (int i = 0; i < 8; i++)
            #pragma unroll
            for (int j = 0; j < 8; j++)
                Wf[which * 32768 + (long)(m0 + ty * 8 + i) * 128 + tx * 8 + j] = to_tf32(acc[i][j]);
    } else if (blk == 6) {
        float* sb = sm;
        for (int i = tid; i < 384; i += 256)
            sb[i] = (i < 128) ? bq1[i] : (i < 256) ? bk1[i - 128] : bv1[i - 256];
        __syncthreads();
        for (int col = tid; col < 384; col += 256) {
            float acc = b_in[col];
            int s = col >> 7;
            for (int k = 0; k < 128; k++)
                acc += sb[s * 128 + k] * Win[k * 384 + col];
            bf[col] = acc;
        }
    } else {
        float* sn = sm;
        float* sh = sm + 32 * 64;
        for (int i = tid; i < 32 * 64; i += 256) sn[i] = num[i];
        __syncthreads();
        for (int i = tid; i < 32 * 256; i += 256) {
            int r = i >> 8, c = i & 255;
            float a = b0[c];
            for (int k = 0; k < 64; k++) a += sn[r * 64 + k] * W0[k * 256 + c];
            sh[i] = tanhf(a);
        }
        __syncthreads();
        for (int i = tid; i < 32 * 128; i += 256) {
            int r = i >> 7, c = i & 127;
            float a = b1[c];
            for (int k = 0; k < 256; k++) a += sh[r * 256 + k] * W1[k * 128 + c];
            hnum[i] = tanhf(a);
        }
    }
}

// ---- build adjacency (bf16), both branches ----------------------------------
__global__ void __launch_bounds__(256) edgebuild2_k(
    const int* __restrict__ ei0, const int* __restrict__ ei1,
    __nv_bfloat16* __restrict__ Abf)
{
    int gidx = blockIdx.x * 256 + threadIdx.x;
    int br = gidx / (B_ * E_);
    int e  = gidx % (B_ * E_);
    const int* ei = br ? ei1 : ei0;
    int b = e / E_;
    long base = (long)br * B_ * N_ * N_ + (long)b * N_ * N_;
    int e0 = ei[2 * e];
    int e1 = ei[2 * e + 1];
    __nv_bfloat16 one = __float2bfloat16(1.0f);
    atomicAdd(&Abf[base + (long)e0 * N_ + e1], one);
    atomicAdd(&Abf[base + (long)e1 * N_ + e0], one);
}

__global__ void zero_k(float* __restrict__ p, long n)
{
    long i = ((long)blockIdx.x * 256 + threadIdx.x) * 4;
    if (i < n) *(float4*)&p[i] = make_float4(0.f, 0.f, 0.f, 0.f);
}

// ---------------- attention: 2-wide online softmax ---------------------------
__global__ void __launch_bounds__(256) attn2_k(
    const float* __restrict__ q2,
    const float* __restrict__ k2,
    const float* __restrict__ v2,
    float* __restrict__ oh)
{
    __shared__ float Ks[256][16];
    __shared__ float Vs[256][16];
    int qt = blockIdx.x, h = blockIdx.y, b = blockIdx.z;
    int tid = threadIdx.x;

    #pragma unroll
    for (int i = 0; i < 4; i++) {
        int idx = tid + i * 256;
        int j  = idx >> 2;
        int d4 = (idx & 3) * 4;
        *(float4*)&Ks[j][d4] = *(const float4*)&k2[(long)(b * KB_ + j) * D_ + h * HD_ + d4];
        *(float4*)&Vs[j][d4] = *(const float4*)&v2[(long)(b * KB_ + j) * D_ + h * HD_ + d4];
    }
    __syncthreads();

    int qi = qt * 256 + tid;
    const float* qp = &q2[(long)(b * N_ + qi) * D_ + h * HD_];
    float q[16];
    #pragma unroll
    for (int d = 0; d < 16; d += 4) {
        float4 v = *(const float4*)&qp[d];
        q[d] = v.x * 0.25f; q[d+1] = v.y * 0.25f; q[d+2] = v.z * 0.25f; q[d+3] = v.w * 0.25f;
    }

    float m = -1e30f, sum = 0.f;
    float o[16];
    #pragma unroll
    for (int d = 0; d < 16; d++) o[d] = 0.f;

    for (int jj = 0; jj < 256; jj += 2) {
        float s0 = 0.f, s1 = 0.f;
        #pragma unroll
        for (int d4 = 0; d4 < 16; d4 += 4) {
            float4 k0v = *(const float4*)&Ks[jj][d4];
            float4 k1v = *(const float4*)&Ks[jj + 1][d4];
            s0 = fmaf(q[d4], k0v.x, s0); s0 = fmaf(q[d4+1], k0v.y, s0);
            s0 = fmaf(q[d4+2], k0v.z, s0); s0 = fmaf(q[d4+3], k0v.w, s0);
            s1 = fmaf(q[d4], k1v.x, s1); s1 = fmaf(q[d4+1], k1v.y, s1);
            s1 = fmaf(q[d4+2], k1v.z, s1); s1 = fmaf(q[d4+3], k1v.w, s1);
        }
        float mx2 = fmaxf(s0, s1);
        if (mx2 > m) {
            float cc = fexp(m - mx2);
            sum *= cc;
            #pragma unroll
            for (int d = 0; d < 16; d++) o[d] *= cc;
            m = mx2;
        }
        float p0 = fexp(s0 - m);
        float p1 = fexp(s1 - m);
        sum += p0 + p1;
        #pragma unroll
        for (int d4 = 0; d4 < 16; d4 += 4) {
            float4 v0 = *(const float4*)&Vs[jj][d4];
            float4 v1 = *(const float4*)&Vs[jj + 1][d4];
            o[d4]   = fmaf(p0, v0.x, fmaf(p1, v1.x, o[d4]));
            o[d4+1] = fmaf(p0, v0.y, fmaf(p1, v1.y, o[d4+1]));
            o[d4+2] = fmaf(p0, v0.z, fmaf(p1, v1.z, o[d4+2]));
            o[d4+3] = fmaf(p0, v0.w, fmaf(p1, v1.w, o[d4+3]));
        }
    }
    float inv = 1.0f / sum;
    float* op = &oh[(long)(b * N_ + qi) * D_ + h * HD_];
    #pragma unroll
    for (int d = 0; d < 16; d += 4)
        *(float4*)&op[d] = make_float4(to_tf32(o[d]*inv), to_tf32(o[d+1]*inv),
                                       to_tf32(o[d+2]*inv), to_tf32(o[d+3]*inv));
}

// ---------------- mean + tail -------------------------------------------------
__global__ void mean1_k(const float* __restrict__ att, float* __restrict__ part)
{
    int b = blockIdx.x, ch = blockIdx.y, c = threadIdx.x;
    float s = 0.f;
    int n0 = ch * 128;
    for (int n = n0; n < n0 + 128; n++)
        s += att[(long)(b * N_ + n) * D_ + c];
    part[(b * 8 + ch) * 128 + c] = s;
}

__global__ void mean2_k(const float* __restrict__ part, float* __restrict__ hmean)
{
    int b = blockIdx.x, c = threadIdx.x;
    float s = 0.f;
    #pragma unroll
    for (int ch = 0; ch < 8; ch++)
        s += part[(b * 8 + ch) * 128 + c];
    hmean[b * 128 + c] = s * (1.0f / N_);
}

__global__ void tail_k(const float* __restrict__ hnum,
                       const float* __restrict__ hmean,
                       const float* __restrict__ stage,
                       float* __restrict__ out)
{
    int i = blockIdx.x * 256 + threadIdx.x;
    if (i < B_ * 258) {
        int b = i / 258, c = i % 258;
        float v = (c < 128) ? hnum[b * 128 + c]
                : (c < 256) ? hmean[b * 128 + (c - 128)]
                            : stage[b * 2 + (c - 256)];
        out[OFF_SV + i] = v;
    }
    if (i < M_) out[OFF_MK + i] = 1.0f;
    if (i < B_ * 2) out[OFF_ST + i] = stage[i];
}

// ---------------- launcher ----------------------------------------------------
extern "C" void kernel_launch(void* const* d_in, const int* in_sizes, int n_in,
                              void* d_out, int out_size)
{
    const float* numerical   = (const float*)d_in[0];
    const float* node_feat   = (const float*)d_in[1];
    const float* stage       = (const float*)d_in[2];
    const float* W_num0      = (const float*)d_in[3];
    const float* b_num0      = (const float*)d_in[4];
    const float* W_num1      = (const float*)d_in[5];
    const float* b_num1      = (const float*)d_in[6];
    const float* W_node      = (const float*)d_in[7];
    const float* b_node      = (const float*)d_in[8];
    const float* pos_enc     = (const float*)d_in[9];
    const float* ew1         = (const float*)d_in[10];
    const float* eb1         = (const float*)d_in[11];
    const float* ew2         = (const float*)d_in[12];
    const float* eb2         = (const float*)d_in[13];
    const float* Wg          = (const float*)d_in[14];
    const float* bg          = (const float*)d_in[15];
    const float* Wu          = (const float*)d_in[16];
    const float* bu          = (const float*)d_in[17];
    const float* Wq1         = (const float*)d_in[18];
    const float* bq1         = (const float*)d_in[19];
    const float* Wk1         = (const float*)d_in[20];
    const float* bk1         = (const float*)d_in[21];
    const float* Wv1         = (const float*)d_in[22];
    const float* bv1         = (const float*)d_in[23];
    const float* Win         = (const float*)d_in[24];
    const float* b_in        = (const float*)d_in[25];
    const float* Wout        = (const float*)d_in[26];
    const float* b_out       = (const float*)d_in[27];
    const int*   ei_dis      = (const int*)d_in[28];
    const int*   ei_od       = (const int*)d_in[29];
    const int*   build_idx   = (const int*)d_in[31];
    float* out = (float*)d_out;

    float *p_h, *p_t, *p_fhb, *p_accb, *p_hb;
    float *p_q2, *p_k2, *p_v2, *p_oh, *p_hnum, *p_hmean, *p_part, *p_Wf, *p_bf, *p_Wr;
    __nv_bfloat16* p_Abf;
    cudaGetSymbolAddress((void**)&p_h,    g_h);
    cudaGetSymbolAddress((void**)&p_t,    g_t);
    cudaGetSymbolAddress((void**)&p_fhb,  g_fhb);
    cudaGetSymbolAddress((void**)&p_accb, g_accb);
    cudaGetSymbolAddress((void**)&p_hb,   g_hb);
    cudaGetSymbolAddress((void**)&p_q2,   g_q2);
    cudaGetSymbolAddress((void**)&p_k2,   g_k2);
    cudaGetSymbolAddress((void**)&p_v2,   g_v2);
    cudaGetSymbolAddress((void**)&p_oh,   g_oh);
    cudaGetSymbolAddress((void**)&p_hnum, g_hnum);
    cudaGetSymbolAddress((void**)&p_hmean,g_hmean);
    cudaGetSymbolAddress((void**)&p_part, g_part);
    cudaGetSymbolAddress((void**)&p_Wf,   g_Wf);
    cudaGetSymbolAddress((void**)&p_bf,   g_bf);
    cudaGetSymbolAddress((void**)&p_Wr,   g_Wr);
    cudaGetSymbolAddress((void**)&p_Abf,  g_Abf);

    // launch order chosen so slot-4 profiling lands on the workhorse tgemm2_k
    round_k<<<WR_TOT / 256, 256>>>(ew1, ew2, Wg, Wu, Wout, p_Wr);                 // 1
    gemm_k<<<256, 256>>>(node_feat, 32, W_node, 128, 0, b_node, p_h, 32, 2, pos_enc); // 2
    pre_k<<<8, 256>>>(Wq1, Wk1, Wv1, Win, bq1, bk1, bv1, b_in,
                      numerical, W_num0, b_num0, W_num1, b_num1,
                      p_Wf, p_bf, p_hnum);                                        // 3
    // edge MLPs, both branches batched per stage
    tgemm2_k<<<dim3(256, 2), 256>>>(p_h, p_h,
                                    p_Wr + WR_E1L0, p_Wr + WR_E2L0,
                                    eb1 + 256, eb2 + 256,
                                    p_t, p_t + M_*D_, 1, 1);                      // 4 (profiled)
    tgemm2_k<<<dim3(256, 2), 256>>>(p_t, p_t + M_*D_,
                                    p_Wr + WR_E1L1, p_Wr + WR_E2L1,
                                    eb1 + 384, eb2 + 384,
                                    p_fhb, p_fhb + M_*D_, 1, 1);                  // 5

    // zero adjacency with kernel (memset node rejected by harness — see R15)
    zero_k<<<(int)((2L*B_*N_*N_/2)/1024), 256>>>((float*)p_Abf, 2L*B_*N_*N_/2);

    // build + aggregate (deg computed in-kernel; acc scaled + rounded)
    edgebuild2_k<<<2*B_*E_/256, 256>>>(ei_dis, ei_od, p_Abf);
    adj_tgemm_k<<<dim3(8, 32, 2), 256>>>(p_Abf, p_fhb, p_accb);

    // fused gate+update+combine
    gu_k<<<dim3(M_/64, 2), 256>>>(p_h, p_accb, p_Wr + WR_WG, bg, p_Wr + WR_WU, bu, p_hb);

    // q2/k2/v2 in one launch
    qkv_k<<<384, 256>>>(p_hb, p_hb + M_*D_, build_idx, p_Wf, p_bf, p_q2, p_k2, p_v2);

    // attention (2-wide online softmax)
    attn2_k<<<dim3(4, H_, B_), 256>>>(p_q2, p_k2, p_v2, p_oh);

    // h_att = oh @ W_out + b_out (final output, unrounded)
    tgemm2_k<<<dim3(256, 1), 256>>>(p_oh, p_oh,
                                    p_Wr + WR_WOUT, p_Wr + WR_WOUT,
                                    b_out, b_out, out, out, 0, 0);

    // mean + tail
    mean1_k<<<dim3(32, 8), 128>>>(out, p_part);
    mean2_k<<<32, 128>>>(p_part, p_hmean);
    tail_k<<<129, 256>>>(p_hnum, p_hmean, stage, out);

    (void)in_sizes; (void)n_in; (void)out_size;
}